// round 17
// baseline (speedup 1.0000x reference)
#include <cuda_runtime.h>
#include <math.h>

// FixedChannelDP via overlap-save FFT convolution.
// y[p,n] = sum_k h[k] x[p,n-k], L=513 taps, output [2, NOUT, 2] f32 (float2).
//
// R15 (3rd submission; broker timeouts): NF=4096 = 8^4 (pure radix-8
// Stockham), 512 threads, payload 3584.
//  - 16% less smem traffic per output, 7% less FFT work per output,
//    36% fewer barriers per output, fewer CTAs (less overlap re-read).
//  - Boundary fusions: gmem-in first stage; FFT1 final (s=512, twiddle-free)
//    + conj*Hc + FFT2 first stage fused in registers; FFT2 final stage writes
//    conj() payload straight to gmem (p=0 octant is the discard region).
//  - Dynamic smem (72 KB) + cudaFuncSetAttribute; __launch_bounds__(512,2).

#define NF      4096
#define OVER    512
#define PAYLOAD 3584
#define THREADS 512

#define PAD(i) ((i) + ((i) >> 3))
#define NFP    4608                   // PAD(4095)=4606 -> 4608 float2 per buffer
#define SMEM_BYTES (2 * NFP * (int)sizeof(float2))   // 73728

__device__ float2 d_Hc[NF];   // conj(FFT_4096(h)) / 4096
__device__ float2 d_TW[NF];   // W_4096^m

__device__ __forceinline__ float2 cmul(float2 a, float2 b) {
    return make_float2(fmaf(a.x, b.x, -a.y * b.y), fmaf(a.x, b.y, a.y * b.x));
}
__device__ __forceinline__ float2 cadd(float2 a, float2 b) { return make_float2(a.x + b.x, a.y + b.y); }
__device__ __forceinline__ float2 csub(float2 a, float2 b) { return make_float2(a.x - b.x, a.y - b.y); }
// conj(x) * h
__device__ __forceinline__ float2 conjmul(float2 x, float2 h) {
    return make_float2(fmaf(x.x, h.x, x.y * h.y), fmaf(x.x, h.y, -x.y * h.x));
}

// In-register DFT-8. a[0..7] -> transformed in natural order.
__device__ __forceinline__ void dft8(float2* a) {
    const float r = 0.70710678118654752440f;
    float2 t0 = cadd(a[0], a[4]), t1 = csub(a[0], a[4]);
    float2 t2 = cadd(a[2], a[6]), t3 = csub(a[2], a[6]);
    float2 t4 = cadd(a[1], a[5]), t5 = csub(a[1], a[5]);
    float2 t6 = cadd(a[3], a[7]), t7 = csub(a[3], a[7]);
    float2 m3 = make_float2(t3.y, -t3.x);
    float2 m7 = make_float2(t7.y, -t7.x);
    float2 e0 = cadd(t0, t2), e2 = csub(t0, t2);
    float2 e1 = cadd(t1, m3), e3 = csub(t1, m3);
    float2 o0 = cadd(t4, t6), o2 = csub(t4, t6);
    float2 o1 = cadd(t5, m7), o3 = csub(t5, m7);
    float2 ro1 = make_float2(r * (o1.x + o1.y), r * (o1.y - o1.x));
    float2 ro2 = make_float2(o2.y, -o2.x);
    float2 ro3 = make_float2(r * (o3.y - o3.x), -r * (o3.x + o3.y));
    a[0] = cadd(e0, o0);  a[4] = csub(e0, o0);
    a[1] = cadd(e1, ro1); a[5] = csub(e1, ro1);
    a[2] = cadd(e2, ro2); a[6] = csub(e2, ro2);
    a[3] = cadd(e3, ro3); a[7] = csub(e3, ro3);
}

// Twiddle chain + scatter for a radix-8 stage (stride s, base js, offset k).
// Uses one LDG (L2-resident d_TW) + chained cmuls.
__device__ __forceinline__ void r8_scatter(float2* dst, const float2* a, int js, int k, int s) {
    float2 w1 = d_TW[js];
    float2 w2 = cmul(w1, w1);
    float2 w3 = cmul(w2, w1);
    float2 w4 = cmul(w2, w2);
    float2 w5 = cmul(w3, w2);
    float2 w6 = cmul(w3, w3);
    float2 w7 = cmul(w4, w3);
    const int ob = 8 * js + k;
    dst[PAD(ob)]         = a[0];
    dst[PAD(ob + s)]     = cmul(w1, a[1]);
    dst[PAD(ob + 2 * s)] = cmul(w2, a[2]);
    dst[PAD(ob + 3 * s)] = cmul(w3, a[3]);
    dst[PAD(ob + 4 * s)] = cmul(w4, a[4]);
    dst[PAD(ob + 5 * s)] = cmul(w5, a[5]);
    dst[PAD(ob + 6 * s)] = cmul(w6, a[6]);
    dst[PAD(ob + 7 * s)] = cmul(w7, a[7]);
}

// smem -> smem radix-8 stage (s in {8, 64}; also s=1 in prep).
__device__ __forceinline__ void r8_s2s(const float2* src, float2* dst, int s, int tid) {
    const int k = tid & (s - 1);
    const int js = tid - k;
    float2 a[8];
#pragma unroll
    for (int q = 0; q < 8; q++) a[q] = src[PAD(tid + q * 512)];
    dft8(a);
    r8_scatter(dst, a, js, k, s);
}

// gmem -> smem radix-8 first stage (s = 1), zero-padded segment load fused.
__device__ __forceinline__ void r8_g2s(const float* __restrict__ xr, const float* __restrict__ xi,
                                       long segStart, int Nn, float2* dst, int tid) {
    float2 a[8];
#pragma unroll
    for (int q = 0; q < 8; q++) {
        long g = segStart + tid + q * 512;
        float2 v = make_float2(0.0f, 0.0f);
        if (g >= 0 && g < (long)Nn) v = make_float2(xr[g], xi[g]);
        a[q] = v;
    }
    dft8(a);
    r8_scatter(dst, a, tid, 0, 1);
}

// FUSED: FFT1 final radix-8 (s=512, twiddle-free) + W = conj(X)*Hc + FFT2
// first radix-8 (s=1). Thread tid holds X[tid + p*512] after the butterfly,
// which are exactly FFT2's first-stage inputs. No smem round trip.
__device__ __forceinline__ void r8hc_r8_fused(const float2* src, float2* dst, int tid) {
    float2 a[8];
#pragma unroll
    for (int q = 0; q < 8; q++) a[q] = src[PAD(tid + q * 512)];
    dft8(a);                                 // X[tid + p*512] = a[p]
#pragma unroll
    for (int p = 0; p < 8; p++) a[p] = conjmul(a[p], d_Hc[tid + p * 512]);
    dft8(a);                                 // FFT2 stage 1 butterfly
    r8_scatter(dst, a, tid, 0, 1);
}

// FFT2 final radix-8 (s=512, twiddle-free), fused with conj() + gmem store.
// p=0 octant (indices < 512) is exactly the overlap/discard region.
__device__ __forceinline__ void r8_out(const float2* src, float2* __restrict__ outp,
                                       long segStart, int NOUT, int tid) {
    float2 a[8];
#pragma unroll
    for (int q = 0; q < 8; q++) a[q] = src[PAD(tid + q * 512)];
    dft8(a);
#pragma unroll
    for (int p = 1; p < 8; p++) {
        long n = segStart + tid + p * 512;
        if (n < (long)NOUT) outp[n] = make_float2(a[p].x, -a[p].y);
    }
}

// ---- Prep (single kernel, 1 CTA): twiddles then Hc = conj(FFT(h)) / NF ----
__global__ void __launch_bounds__(THREADS)
prep_kernel(const float* __restrict__ hre, const float* __restrict__ him, int L)
{
    extern __shared__ float2 smem[];
    float2* A = smem;
    float2* B = smem + NFP;
    const int tid = threadIdx.x;

    // Twiddles: W_4096^m = exp(-i*pi*m/2048), exact fp32 argument.
    for (int m = tid; m < NF; m += THREADS) {
        float sv, cv;
        sincospif(-(float)m / 2048.0f, &sv, &cv);
        d_TW[m] = make_float2(cv, sv);
    }
    for (int i = tid; i < NF; i += THREADS) {
        float2 v = make_float2(0.0f, 0.0f);
        if (i < L) v = make_float2(hre[i], him[i]);
        A[PAD(i)] = v;
    }
    __syncthreads();   // orders d_TW (global) and A (shared) within the CTA

    r8_s2s(A, B, 1,  tid); __syncthreads();
    r8_s2s(B, A, 8,  tid); __syncthreads();
    r8_s2s(A, B, 64, tid); __syncthreads();

    // Final radix-8 (s=512, twiddle-free) -> Hc
    float2 a[8];
#pragma unroll
    for (int q = 0; q < 8; q++) a[q] = B[PAD(tid + q * 512)];
    dft8(a);
    const float sc = 1.0f / (float)NF;
#pragma unroll
    for (int p = 0; p < 8; p++)
        d_Hc[tid + p * 512] = make_float2(a[p].x * sc, -a[p].y * sc);
}

// ---- Main kernel: overlap-save tile, fully fused ----
__global__ void __launch_bounds__(THREADS, 2)
conv_fft_kernel(const float* __restrict__ txr, const float* __restrict__ txi,
                float2* __restrict__ out, int N, int NOUT)
{
    extern __shared__ float2 smem[];
    float2* A = smem;
    float2* B = smem + NFP;
    const int tid = threadIdx.x;
    const int pol = blockIdx.y;
    const long segStart = (long)blockIdx.x * PAYLOAD - OVER;
    const float* __restrict__ xr = txr + (size_t)pol * N;
    const float* __restrict__ xi = txi + (size_t)pol * N;

    // FFT1 (gmem in)
    r8_g2s(xr, xi, segStart, N, B, tid); __syncthreads();
    r8_s2s(B, A, 8,  tid);               __syncthreads();
    r8_s2s(A, B, 64, tid);               __syncthreads();
    // FFT1 final r8 + Hc + FFT2 first r8, fused in registers
    r8hc_r8_fused(B, A, tid);            __syncthreads();
    // FFT2 remainder (gmem out with conj fused at the end)
    r8_s2s(A, B, 8,  tid);               __syncthreads();
    r8_s2s(B, A, 64, tid);               __syncthreads();
    r8_out(A, out + (size_t)pol * NOUT, segStart, NOUT, tid);
}

extern "C" void kernel_launch(void* const* d_in, const int* in_sizes, int n_in,
                              void* d_out, int out_size)
{
    const float* txr = (const float*)d_in[0];  // [2, N]
    const float* txi = (const float*)d_in[1];  // [2, N]
    const float* hre = (const float*)d_in[2];  // [L]
    const float* him = (const float*)d_in[3];  // [L]

    const int N    = in_sizes[0] / 2;
    const int L    = in_sizes[2];              // 513 (scheme requires L-1 <= OVER)
    const int NOUT = N + L - 1;

    // Opt-in to 72 KB dynamic smem (idempotent; host-side attribute, no alloc).
    cudaFuncSetAttribute(prep_kernel, cudaFuncAttributeMaxDynamicSharedMemorySize, SMEM_BYTES);
    cudaFuncSetAttribute(conv_fft_kernel, cudaFuncAttributeMaxDynamicSharedMemorySize, SMEM_BYTES);

    prep_kernel<<<1, THREADS, SMEM_BYTES>>>(hre, him, L);

    const int tiles = (NOUT + PAYLOAD - 1) / PAYLOAD;
    dim3 grid(tiles, 2);
    conv_fft_kernel<<<grid, THREADS, SMEM_BYTES>>>(txr, txi, (float2*)d_out, N, NOUT);
}